// round 16
// baseline (speedup 1.0000x reference)
#include <cuda_runtime.h>

// ---------------- problem constants ----------------
#define Gn   128
#define NPG  256
#define EPG  4096
#define Nn   (Gn*NPG)          // 32768 nodes
#define En   (Gn*EPG)          // 524288 edges
#define Kk   2048              // kept edges per group
#define GKn  (Gn*Kk)           // 262144

// output layout (all f32, flattened tuple in reference order)
#define OFF_SCORE 0
#define OFF_CW    (En)
#define OFF_DW    (En + GKn)
#define OFF_CEI   (En + 2*GKn)
#define OFF_FEI   (En + 4*GKn)
#define OFF_CMASK (En + 6*GKn)
#define OFF_FMASK (En + 6*GKn + Nn)

// ---------------- device scratch ----------------
__device__ float g_A[Nn*64];
__device__ float g_B[Nn*64];
__device__ float g_C[Nn*64];
__device__ float g_H1[Nn*64];
__device__ float g_H2[Nn*64];
__device__ float g_PA[Nn*256];
__device__ float g_PB[Nn*256];
__device__ int   g_rows[En];      // LOCAL src node id (0..255)
__device__ float g_ews[En];
__device__ int   g_start[Nn];
__device__ int   g_keepnodes[2*GKn];
__device__ int   g_dropnodes[2*GKn];
__device__ int   g_presC[Nn];
__device__ int   g_presD[Nn];
__device__ int   g_nidC[Nn];
__device__ int   g_nidD[Nn];
__device__ int   g_bsC[32];
__device__ int   g_bsD[32];

// ---------------- helpers ----------------
__device__ __forceinline__ int warp_incl_scan(int v) {
    int lane = threadIdx.x & 31;
#pragma unroll
    for (int o = 1; o < 32; o <<= 1) {
        int t = __shfl_up_sync(0xffffffffu, v, o);
        if (lane >= o) v += t;
    }
    return v;
}

__device__ __forceinline__ void fma2(unsigned long long& d, unsigned long long a, unsigned long long b) {
    asm("fma.rn.f32x2 %0, %1, %2, %0;" : "+l"(d) : "l"(a), "l"(b));
}
__device__ __forceinline__ unsigned long long add2(unsigned long long a, unsigned long long b) {
    unsigned long long d;
    asm("add.rn.f32x2 %0, %1, %2;" : "=l"(d) : "l"(a), "l"(b));
    return d;
}
__device__ __forceinline__ unsigned long long relu2(unsigned long long a) {
    float lo, hi;
    asm("mov.b64 {%0,%1}, %2;" : "=f"(lo), "=f"(hi) : "l"(a));
    lo = fmaxf(lo, 0.f);
    hi = fmaxf(hi, 0.f);
    unsigned long long d;
    asm("mov.b64 %0, {%1,%2};" : "=l"(d) : "f"(lo), "f"(hi));
    return d;
}
__device__ __forceinline__ float2 up2(unsigned long long v) {
    float2 f;
    asm("mov.b64 {%0,%1}, %2;" : "=f"(f.x), "=f"(f.y) : "l"(v));
    return f;
}
__device__ __forceinline__ float red2(unsigned long long v) {
    float2 f = up2(v);
    return f.x + f.y;
}

// ---------------- deterministic per-group CSR (counting sort by dst) + zero pres ----------------
__global__ void __launch_bounds__(256) csr_build_k(const int* __restrict__ ei,
                                                   const float* __restrict__ ea) {
    __shared__ int hist[8][256];
    __shared__ int wsums[8];
    int g = blockIdx.x, tid = threadIdx.x;
    int w = tid >> 5, lane = tid & 31;
    int base = g * EPG;

    g_presC[g * NPG + tid] = 0;
    g_presD[g * NPG + tid] = 0;

#pragma unroll
    for (int i = 0; i < 8; i++) hist[i][tid] = 0;
    __syncthreads();

    for (int rnd = 0; rnd < 16; rnd++) {
        int j = w * 512 + rnd * 32 + lane;
        int c = ei[En + base + j] - g * NPG;
        atomicAdd(&hist[w][c], 1);
    }
    __syncthreads();

    int s = 0;
#pragma unroll
    for (int i = 0; i < 8; i++) { int h = hist[i][tid]; hist[i][tid] = s; s += h; }
    int incl = warp_incl_scan(s);
    if (lane == 31) wsums[w] = incl;
    __syncthreads();
    if (tid == 0) { int a = 0; for (int i = 0; i < 8; i++) { int t = wsums[i]; wsums[i] = a; a += t; } }
    __syncthreads();
    int excl_c = incl - s + wsums[w];
    g_start[g * NPG + tid] = base + excl_c;
#pragma unroll
    for (int i = 0; i < 8; i++) hist[i][tid] += excl_c;
    __syncthreads();

    for (int rnd = 0; rnd < 16; rnd++) {
        int j = w * 512 + rnd * 32 + lane;
        int r = ei[base + j] - g * NPG;          // LOCAL id
        int c = ei[En + base + j] - g * NPG;
        float wv = ea[base + j];
        unsigned mask = __match_any_sync(0xffffffffu, c);
        int rank = __popc(mask & ((1u << lane) - 1u));
        int cur = hist[w][c];
        __syncwarp();
        if (lane == (__ffs(mask) - 1)) hist[w][c] = cur + __popc(mask);
        g_rows[base + cur + rank] = r;
        g_ews[base + cur + rank]  = wv;
        __syncwarp();
    }
}

// ================= stride-68 linear f32x2 GEMM core (R10-proven 4v x 4f) =================
#define TSTR 68

__device__ __forceinline__ void gemm_core(const float* __restrict__ Xs,
                                          const float* __restrict__ Ws,
                                          int tf, int tv,
                                          unsigned long long acc[4][4]) {
    const float* xb0 = &Xs[tv * TSTR];
    const float* wb0 = &Ws[tf * TSTR];
#pragma unroll 4
    for (int gk = 0; gk < 16; gk++) {
        ulonglong2 xq[4], wq[4];
#pragma unroll
        for (int i = 0; i < 4; i++)
            xq[i] = *(const ulonglong2*)(xb0 + i * (16 * TSTR) + gk * 4);
#pragma unroll
        for (int j = 0; j < 4; j++)
            wq[j] = *(const ulonglong2*)(wb0 + j * (16 * TSTR) + gk * 4);
#pragma unroll
        for (int i = 0; i < 4; i++)
#pragma unroll
            for (int j = 0; j < 4; j++) {
                fma2(acc[i][j], xq[i].x, wq[j].x);
                fma2(acc[i][j], xq[i].y, wq[j].y);
            }
    }
}

// load a 64x64 tile (row stride lds in gmem) into stride-68 smem
__device__ __forceinline__ void load_tile(float* __restrict__ dst,
                                          const float* __restrict__ src, int lds,
                                          int tid) {
#pragma unroll
    for (int t = tid; t < 1024; t += 256) {
        int row = t >> 4, g = t & 15;
        *(float4*)&dst[row * TSTR + g * 4] = *(const float4*)&src[row * lds + g * 4];
    }
}

// leconv layer, merged outputs: grid Nn/64. Xs loaded once; loop m=0..2 over W1/W2/W3.
__global__ void __launch_bounds__(256) gemmL_k(const float* __restrict__ X,
                                               const float* __restrict__ W1,
                                               const float* __restrict__ b1,
                                               const float* __restrict__ W2,
                                               const float* __restrict__ W3,
                                               const float* __restrict__ b3) {
    __shared__ __align__(16) float Xs[64 * TSTR];
    __shared__ __align__(16) float Ws[64 * TSTR];
    int tid = threadIdx.x;
    int vtile = blockIdx.x * 64;

    load_tile(Xs, X + vtile * 64, 64, tid);

    int tf = tid & 15, tv = tid >> 4;

#pragma unroll 1
    for (int m = 0; m < 3; m++) {
        const float* W = (m == 0) ? W1 : ((m == 1) ? W2 : W3);
        const float* bias = (m == 0) ? b1 : ((m == 2) ? b3 : nullptr);
        float* Y = (m == 0) ? g_A : ((m == 1) ? g_B : g_C);

        load_tile(Ws, W, 64, tid);
        __syncthreads();

        unsigned long long acc[4][4];
#pragma unroll
        for (int i = 0; i < 4; i++)
#pragma unroll
            for (int j = 0; j < 4; j++) acc[i][j] = 0ull;

        gemm_core(Xs, Ws, tf, tv, acc);

        float bj[4] = {0.f, 0.f, 0.f, 0.f};
        if (bias) {
#pragma unroll
            for (int j = 0; j < 4; j++) bj[j] = bias[tf + 16 * j];
        }
#pragma unroll
        for (int i = 0; i < 4; i++)
#pragma unroll
            for (int j = 0; j < 4; j++)
                Y[(vtile + tv + 16 * i) * 64 + tf + 16 * j] = red2(acc[i][j]) + bj[j];
        __syncthreads();   // Ws consumed before next iteration overwrites
    }
}

// MLP projection, merged f-tiles: grid (Nn/64, 2): y=0 -> PA, y=1 -> PB. (R15-proven)
__global__ void __launch_bounds__(256) gemmM_k(const float* __restrict__ X,
                                               const float* __restrict__ Wm1,
                                               const float* __restrict__ bm1) {
    __shared__ __align__(16) float Xs[64 * TSTR];
    __shared__ __align__(16) float Ws[64 * TSTR];
    int tid = threadIdx.x;
    int vtile = blockIdx.x * 64;
    int isB = blockIdx.y;
    int koff = isB ? 64 : 0;
    float* Y = isB ? g_PB : g_PA;

    load_tile(Xs, X + vtile * 64, 64, tid);

    int tf = tid & 15, tv = tid >> 4;

#pragma unroll 1
    for (int ft = 0; ft < 4; ft++) {
        int ftile = ft * 64;
        load_tile(Ws, Wm1 + ftile * 128 + koff, 128, tid);
        __syncthreads();

        unsigned long long acc[4][4];
#pragma unroll
        for (int i = 0; i < 4; i++)
#pragma unroll
            for (int j = 0; j < 4; j++) acc[i][j] = 0ull;

        gemm_core(Xs, Ws, tf, tv, acc);

        float bj[4] = {0.f, 0.f, 0.f, 0.f};
        if (!isB) {
#pragma unroll
            for (int j = 0; j < 4; j++) bj[j] = bm1[ftile + tf + 16 * j];
        }
#pragma unroll
        for (int i = 0; i < 4; i++)
#pragma unroll
            for (int j = 0; j < 4; j++)
                Y[(vtile + tv + 16 * i) * 256 + ftile + tf + 16 * j] = red2(acc[i][j]) + bj[j];
        __syncthreads();
    }
}

// ---------------- gather-aggregate + combine, 4x unrolled (R10-proven) -------------
__global__ void aggc_k(const float* __restrict__ A, const float* __restrict__ B,
                       const float* __restrict__ C, float* __restrict__ H, int doRelu) {
    int warp = blockIdx.x * (blockDim.x >> 5) + (threadIdx.x >> 5);
    int lane = threadIdx.x & 31;
    if (warp >= Nn) return;
    int v = warp;
    int s = g_start[v];
    int g = v >> 8;
    int e = ((v & 255) == 255) ? (g * EPG + EPG) : g_start[v + 1];
    int abase = g * NPG * 64;
    float2 acc = make_float2(0.f, 0.f);
    float ws = 0.f;
    int i = s;
    for (; i + 4 <= e; i += 4) {
        int r0 = g_rows[i],     r1 = g_rows[i + 1];
        int r2 = g_rows[i + 2], r3 = g_rows[i + 3];
        float w0 = g_ews[i],     w1 = g_ews[i + 1];
        float w2 = g_ews[i + 2], w3 = g_ews[i + 3];
        float2 a0 = *(const float2*)&A[abase + r0 * 64 + lane * 2];
        float2 a1 = *(const float2*)&A[abase + r1 * 64 + lane * 2];
        float2 a2 = *(const float2*)&A[abase + r2 * 64 + lane * 2];
        float2 a3 = *(const float2*)&A[abase + r3 * 64 + lane * 2];
        acc.x += w0 * a0.x + w1 * a1.x + w2 * a2.x + w3 * a3.x;
        acc.y += w0 * a0.y + w1 * a1.y + w2 * a2.y + w3 * a3.y;
        ws += w0 + w1 + w2 + w3;
    }
    for (; i < e; i++) {
        int r = g_rows[i];
        float w = g_ews[i];
        float2 a = *(const float2*)&A[abase + r * 64 + lane * 2];
        acc.x += w * a.x;
        acc.y += w * a.y;
        ws += w;
    }
    float2 bv = *(const float2*)&B[v * 64 + lane * 2];
    float2 cv = *(const float2*)&C[v * 64 + lane * 2];
    float hx = acc.x - ws * bv.x + cv.x;
    float hy = acc.y - ws * bv.y + cv.y;
    if (doRelu) { hx = fmaxf(hx, 0.f); hy = fmaxf(hy, 0.f); }
    *(float2*)&H[v * 64 + lane * 2] = make_float2(hx, hy);
}

// ---------------- per-edge score: smem-staged packed-f32x2 relu-dot (R10 config) ----------------
#define ESTRIDE 68
__global__ void __launch_bounds__(512) edge_score_k(const int* __restrict__ ei,
                                                    const float* __restrict__ PA,
                                                    const float* __restrict__ PB,
                                                    const float* __restrict__ Wm2,
                                                    const float* __restrict__ bm2,
                                                    float* __restrict__ out) {
    extern __shared__ float sm[];
    float* pa_s = sm;                     // 256*ESTRIDE
    float* pb_s = sm + 256 * ESTRIDE;     // 256*ESTRIDE
    __shared__ __align__(16) float wm2s[256];
    int g = blockIdx.x, tid = threadIdx.x;
    if (tid < 256) wm2s[tid] = Wm2[tid];
    int base = g * EPG;

    int r[8], c[8];
    unsigned long long acc2[8];
#pragma unroll
    for (int i = 0; i < 8; i++) {
        int j = tid + i * 512;
        r[i] = ei[base + j] - g * NPG;
        c[i] = ei[En + base + j] - g * NPG;
        acc2[i] = 0ull;
    }

    for (int p = 0; p < 4; p++) {
        __syncthreads();
        for (int t = tid; t < 4096; t += 512) {
            int nd = t >> 4, kk = (t & 15) * 4;
            *(float4*)&pa_s[nd * ESTRIDE + kk] = *(const float4*)&PA[(g * NPG + nd) * 256 + p * 64 + kk];
            *(float4*)&pb_s[nd * ESTRIDE + kk] = *(const float4*)&PB[(g * NPG + nd) * 256 + p * 64 + kk];
        }
        __syncthreads();
#pragma unroll 4
        for (int kk = 0; kk < 64; kk += 4) {
            ulonglong2 w2 = *(const ulonglong2*)&wm2s[p * 64 + kk];
#pragma unroll
            for (int i = 0; i < 8; i++) {
                ulonglong2 va = *(const ulonglong2*)&pa_s[r[i] * ESTRIDE + kk];
                ulonglong2 vb = *(const ulonglong2*)&pb_s[c[i] * ESTRIDE + kk];
                unsigned long long s0 = relu2(add2(va.x, vb.x));
                unsigned long long s1 = relu2(add2(va.y, vb.y));
                fma2(acc2[i], s0, w2.x);
                fma2(acc2[i], s1, w2.y);
            }
        }
    }
    float bb = bm2[0];
#pragma unroll
    for (int i = 0; i < 8; i++) out[base + tid + i * 512] = red2(acc2[i]) + bb;
}

// ---------------- per-group stable bitonic argsort (R10 smem version) ----------------
__global__ void __launch_bounds__(1024) sort_k(const int* __restrict__ ei,
                                               float* __restrict__ out) {
    __shared__ unsigned long long keys[EPG];
    int g = blockIdx.x, tid = threadIdx.x;
    int base = g * EPG;
    for (int j = tid; j < EPG; j += 1024) {
        float s = out[base + j];
        unsigned int b = __float_as_uint(s);
        unsigned int enc = (b & 0x80000000u) ? ~b : (b | 0x80000000u);
        keys[j] = (((unsigned long long)(~enc)) << 32) | (unsigned int)j;
    }
    __syncthreads();
    for (int size = 2; size <= EPG; size <<= 1) {
        for (int stride = size >> 1; stride > 0; stride >>= 1) {
#pragma unroll 2
            for (int t = tid; t < EPG / 2; t += 1024) {
                int lo = ((t & ~(stride - 1)) << 1) | (t & (stride - 1));
                int hi = lo + stride;
                bool asc = ((lo & size) == 0);
                unsigned long long a = keys[lo], b = keys[hi];
                bool sw = asc ? (a > b) : (a < b);
                if (sw) { keys[lo] = b; keys[hi] = a; }
            }
            __syncthreads();
        }
    }
    for (int i2 = tid; i2 < EPG; i2 += 1024) {
        unsigned long long kv = keys[i2];
        int j = (int)(kv & 0xffffffffull);
        unsigned int enc = ~(unsigned int)(kv >> 32);
        unsigned int sb = (enc & 0x80000000u) ? (enc & 0x7fffffffu) : ~enc;
        float s = __uint_as_float(sb);
        int e = base + j;
        int rs = ei[e];
        int rd = ei[En + e];
        if (i2 < Kk) {
            int o = g * Kk + i2;
            out[OFF_CW + o] = s;
            g_keepnodes[o] = rs;
            g_keepnodes[GKn + o] = rd;
            g_presC[rs] = 1;
            g_presC[rd] = 1;
        } else {
            int o = g * Kk + (i2 - Kk);
            out[OFF_DW + o] = -s;
            g_dropnodes[o] = rs;
            g_dropnodes[GKn + o] = rd;
            g_presD[rs] = 1;
            g_presD[rd] = 1;
        }
    }
}

// ---------------- merged scans (y=0: causal, y=1: conf) — R10-proven ----------------
__global__ void __launch_bounds__(1024) scan1_k() {
    __shared__ int ws_[32];
    const int* pres = blockIdx.y ? g_presD : g_presC;
    int* nid = blockIdx.y ? g_nidD : g_nidC;
    int* bsum = blockIdx.y ? g_bsD : g_bsC;
    int i = blockIdx.x * 1024 + threadIdx.x;
    int x = pres[i];
    int v = warp_incl_scan(x);
    int w = threadIdx.x >> 5, lane = threadIdx.x & 31;
    if (lane == 31) ws_[w] = v;
    __syncthreads();
    if (w == 0) { int t = ws_[lane]; t = warp_incl_scan(t); ws_[lane] = t; }
    __syncthreads();
    if (w > 0) v += ws_[w - 1];
    nid[i] = v;
    if (threadIdx.x == 1023) bsum[blockIdx.x] = v;
}

__global__ void scan2_k() {
    int* bsum = (threadIdx.x >= 32) ? g_bsD : g_bsC;
    int idx = threadIdx.x & 31;
    int x = bsum[idx];
    int v = warp_incl_scan(x);
    bsum[idx] = v - x;
}

__global__ void __launch_bounds__(1024) scan3_k(float* __restrict__ out) {
    const int* pres = blockIdx.y ? g_presD : g_presC;
    int* nid = blockIdx.y ? g_nidD : g_nidC;
    const int* bsum = blockIdx.y ? g_bsD : g_bsC;
    float* maskOut = out + (blockIdx.y ? OFF_FMASK : OFF_CMASK);
    int i = blockIdx.x * 1024 + threadIdx.x;
    nid[i] = nid[i] + bsum[blockIdx.x] - 1;
    maskOut[i] = (float)pres[i];
}

// ---------------- final relabeled-edge gather ----------------
__global__ void gather_k(float* __restrict__ out) {
    int i = blockIdx.x * blockDim.x + threadIdx.x;
    if (i >= 2 * GKn) return;
    out[OFF_CEI + i] = (float)g_nidC[g_keepnodes[i]];
    out[OFF_FEI + i] = (float)g_nidD[g_dropnodes[i]];
}

// ---------------- host launch ----------------
extern "C" void kernel_launch(void* const* d_in, const int* in_sizes, int n_in,
                              void* d_out, int out_size) {
    const float* x   = (const float*)d_in[0];
    const float* ea  = (const float*)d_in[1];
    const float* W11 = (const float*)d_in[2];
    const float* b11 = (const float*)d_in[3];
    const float* W12 = (const float*)d_in[4];
    const float* W13 = (const float*)d_in[5];
    const float* b13 = (const float*)d_in[6];
    const float* W21 = (const float*)d_in[7];
    const float* b21 = (const float*)d_in[8];
    const float* W22 = (const float*)d_in[9];
    const float* W23 = (const float*)d_in[10];
    const float* b23 = (const float*)d_in[11];
    const float* Wm1 = (const float*)d_in[12];
    const float* bm1 = (const float*)d_in[13];
    const float* Wm2 = (const float*)d_in[14];
    const float* bm2 = (const float*)d_in[15];
    const int*   ei  = (const int*)d_in[16];   // int32 (JAX x64 disabled)
    float* out = (float*)d_out;

    float *A, *B, *C, *H1, *H2, *PA, *PB;
    cudaGetSymbolAddress((void**)&A, g_A);
    cudaGetSymbolAddress((void**)&B, g_B);
    cudaGetSymbolAddress((void**)&C, g_C);
    cudaGetSymbolAddress((void**)&H1, g_H1);
    cudaGetSymbolAddress((void**)&H2, g_H2);
    cudaGetSymbolAddress((void**)&PA, g_PA);
    cudaGetSymbolAddress((void**)&PB, g_PB);

    const int esSmem = 2 * 256 * ESTRIDE * sizeof(float); // 136 KB
    cudaFuncSetAttribute(edge_score_k, cudaFuncAttributeMaxDynamicSharedMemorySize, esSmem);

    csr_build_k<<<Gn, 256>>>(ei, ea);

    // ---- leconv 1 ----
    gemmL_k<<<Nn / 64, 256>>>(x, W11, b11, W12, W13, b13);
    aggc_k<<<Nn / 8, 256>>>(A, B, C, H1, 1);

    // ---- leconv 2 ----
    gemmL_k<<<Nn / 64, 256>>>(H1, W21, b21, W22, W23, b23);
    aggc_k<<<Nn / 8, 256>>>(A, B, C, H2, 0);

    // ---- MLP node projections (PA | PB), merged f-tiles ----
    gemmM_k<<<dim3(Nn / 64, 2), 256>>>(H2, Wm1, bm1);

    // ---- per-edge scores ----
    edge_score_k<<<Gn, 512, esSmem>>>(ei, PA, PB, Wm2, bm2, out);

    // ---- per-group sort + keep/drop split ----
    sort_k<<<Gn, 1024>>>(ei, out);

    // ---- relabel scans (both graphs, merged) ----
    scan1_k<<<dim3(32, 2), 1024>>>();
    scan2_k<<<1, 64>>>();
    scan3_k<<<dim3(32, 2), 1024>>>(out);

    // ---- relabeled edge index gather ----
    gather_k<<<(2 * GKn) / 256, 256>>>(out);
}

// round 17
// speedup vs baseline: 1.0514x; 1.0514x over previous
#include <cuda_runtime.h>

// ---------------- problem constants ----------------
#define Gn   128
#define NPG  256
#define EPG  4096
#define Nn   (Gn*NPG)          // 32768 nodes
#define En   (Gn*EPG)          // 524288 edges
#define Kk   2048              // kept edges per group
#define GKn  (Gn*Kk)           // 262144

// output layout (all f32, flattened tuple in reference order)
#define OFF_SCORE 0
#define OFF_CW    (En)
#define OFF_DW    (En + GKn)
#define OFF_CEI   (En + 2*GKn)
#define OFF_FEI   (En + 4*GKn)
#define OFF_CMASK (En + 6*GKn)
#define OFF_FMASK (En + 6*GKn + Nn)

// ---------------- device scratch ----------------
__device__ float g_A[Nn*64];
__device__ float g_B[Nn*64];
__device__ float g_C[Nn*64];
__device__ float g_H1[Nn*64];
__device__ float g_H2[Nn*64];
__device__ float g_PA[Nn*256];
__device__ float g_PB[Nn*256];
__device__ int   g_rows[En];      // LOCAL src node id (0..255)
__device__ float g_ews[En];
__device__ int   g_start[Nn];
__device__ int   g_keepnodes[2*GKn];
__device__ int   g_dropnodes[2*GKn];
__device__ int   g_presC[Nn];
__device__ int   g_presD[Nn];
__device__ int   g_nidC[Nn];
__device__ int   g_nidD[Nn];
__device__ int   g_bsC[32];
__device__ int   g_bsD[32];

// ---------------- helpers ----------------
__device__ __forceinline__ int warp_incl_scan(int v) {
    int lane = threadIdx.x & 31;
#pragma unroll
    for (int o = 1; o < 32; o <<= 1) {
        int t = __shfl_up_sync(0xffffffffu, v, o);
        if (lane >= o) v += t;
    }
    return v;
}

__device__ __forceinline__ void fma2(unsigned long long& d, unsigned long long a, unsigned long long b) {
    asm("fma.rn.f32x2 %0, %1, %2, %0;" : "+l"(d) : "l"(a), "l"(b));
}
__device__ __forceinline__ unsigned long long add2(unsigned long long a, unsigned long long b) {
    unsigned long long d;
    asm("add.rn.f32x2 %0, %1, %2;" : "=l"(d) : "l"(a), "l"(b));
    return d;
}
__device__ __forceinline__ unsigned long long relu2(unsigned long long a) {
    float lo, hi;
    asm("mov.b64 {%0,%1}, %2;" : "=f"(lo), "=f"(hi) : "l"(a));
    lo = fmaxf(lo, 0.f);
    hi = fmaxf(hi, 0.f);
    unsigned long long d;
    asm("mov.b64 %0, {%1,%2};" : "=l"(d) : "f"(lo), "f"(hi));
    return d;
}
__device__ __forceinline__ float2 up2(unsigned long long v) {
    float2 f;
    asm("mov.b64 {%0,%1}, %2;" : "=f"(f.x), "=f"(f.y) : "l"(v));
    return f;
}
__device__ __forceinline__ float red2(unsigned long long v) {
    float2 f = up2(v);
    return f.x + f.y;
}

// ================= stride-68 linear f32x2 GEMM core (R10-proven 4v x 4f) =================
#define TSTR 68

__device__ __forceinline__ void gemm_core(const float* __restrict__ Xs,
                                          const float* __restrict__ Ws,
                                          int tf, int tv,
                                          unsigned long long acc[4][4]) {
    const float* xb0 = &Xs[tv * TSTR];
    const float* wb0 = &Ws[tf * TSTR];
#pragma unroll 4
    for (int gk = 0; gk < 16; gk++) {
        ulonglong2 xq[4], wq[4];
#pragma unroll
        for (int i = 0; i < 4; i++)
            xq[i] = *(const ulonglong2*)(xb0 + i * (16 * TSTR) + gk * 4);
#pragma unroll
        for (int j = 0; j < 4; j++)
            wq[j] = *(const ulonglong2*)(wb0 + j * (16 * TSTR) + gk * 4);
#pragma unroll
        for (int i = 0; i < 4; i++)
#pragma unroll
            for (int j = 0; j < 4; j++) {
                fma2(acc[i][j], xq[i].x, wq[j].x);
                fma2(acc[i][j], xq[i].y, wq[j].y);
            }
    }
}

// load a 64x64 tile (row stride lds in gmem) into stride-68 smem
__device__ __forceinline__ void load_tile(float* __restrict__ dst,
                                          const float* __restrict__ src, int lds,
                                          int tid) {
#pragma unroll
    for (int t = tid; t < 1024; t += 256) {
        int row = t >> 4, g = t & 15;
        *(float4*)&dst[row * TSTR + g * 4] = *(const float4*)&src[row * lds + g * 4];
    }
}

// gemm body shared by fused + plain leconv kernels
__device__ __forceinline__ void gemmL_body(float* sm, int vtile, int m, int tid,
                                           const float* __restrict__ X,
                                           const float* __restrict__ W1,
                                           const float* __restrict__ b1,
                                           const float* __restrict__ W2,
                                           const float* __restrict__ W3,
                                           const float* __restrict__ b3) {
    float* Xs = sm;
    float* Ws = sm + 64 * TSTR;
    const float* W = (m == 0) ? W1 : ((m == 1) ? W2 : W3);
    const float* bias = (m == 0) ? b1 : ((m == 2) ? b3 : nullptr);
    float* Y = (m == 0) ? g_A : ((m == 1) ? g_B : g_C);

    load_tile(Xs, X + vtile * 64, 64, tid);
    load_tile(Ws, W, 64, tid);
    __syncthreads();

    int tf = tid & 15, tv = tid >> 4;
    unsigned long long acc[4][4];
#pragma unroll
    for (int i = 0; i < 4; i++)
#pragma unroll
        for (int j = 0; j < 4; j++) acc[i][j] = 0ull;

    gemm_core(Xs, Ws, tf, tv, acc);

    float bj[4] = {0.f, 0.f, 0.f, 0.f};
    if (bias) {
#pragma unroll
        for (int j = 0; j < 4; j++) bj[j] = bias[tf + 16 * j];
    }
#pragma unroll
    for (int i = 0; i < 4; i++)
#pragma unroll
        for (int j = 0; j < 4; j++)
            Y[(vtile + tv + 16 * i) * 64 + tf + 16 * j] = red2(acc[i][j]) + bj[j];
}

// csr body (R10-proven counting sort)
__device__ __forceinline__ void csr_body(int* smI, int g, int tid,
                                         const int* __restrict__ ei,
                                         const float* __restrict__ ea) {
    int (*hist)[256] = (int(*)[256])smI;
    int* wsums = smI + 8 * 256;
    int w = tid >> 5, lane = tid & 31;
    int base = g * EPG;

    g_presC[g * NPG + tid] = 0;
    g_presD[g * NPG + tid] = 0;

#pragma unroll
    for (int i = 0; i < 8; i++) hist[i][tid] = 0;
    __syncthreads();

    for (int rnd = 0; rnd < 16; rnd++) {
        int j = w * 512 + rnd * 32 + lane;
        int c = ei[En + base + j] - g * NPG;
        atomicAdd(&hist[w][c], 1);
    }
    __syncthreads();

    int s = 0;
#pragma unroll
    for (int i = 0; i < 8; i++) { int h = hist[i][tid]; hist[i][tid] = s; s += h; }
    int incl = warp_incl_scan(s);
    if (lane == 31) wsums[w] = incl;
    __syncthreads();
    if (tid == 0) { int a = 0; for (int i = 0; i < 8; i++) { int t = wsums[i]; wsums[i] = a; a += t; } }
    __syncthreads();
    int excl_c = incl - s + wsums[w];
    g_start[g * NPG + tid] = base + excl_c;
#pragma unroll
    for (int i = 0; i < 8; i++) hist[i][tid] += excl_c;
    __syncthreads();

    for (int rnd = 0; rnd < 16; rnd++) {
        int j = w * 512 + rnd * 32 + lane;
        int r = ei[base + j] - g * NPG;          // LOCAL id
        int c = ei[En + base + j] - g * NPG;
        float wv = ea[base + j];
        unsigned mask = __match_any_sync(0xffffffffu, c);
        int rank = __popc(mask & ((1u << lane) - 1u));
        int cur = hist[w][c];
        __syncwarp();
        if (lane == (__ffs(mask) - 1)) hist[w][c] = cur + __popc(mask);
        g_rows[base + cur + rank] = r;
        g_ews[base + cur + rank]  = wv;
        __syncwarp();
    }
}

// FUSED: blocks [0,1536) = leconv-1 gemm (vtile = bx%512, m = bx/512);
//        blocks [1536,1664) = csr build for group bx-1536.
__global__ void __launch_bounds__(256) fused1_k(const float* __restrict__ X,
                                                const float* __restrict__ W1,
                                                const float* __restrict__ b1,
                                                const float* __restrict__ W2,
                                                const float* __restrict__ W3,
                                                const float* __restrict__ b3,
                                                const int* __restrict__ ei,
                                                const float* __restrict__ ea) {
    extern __shared__ __align__(16) float smf[];
    int bx = blockIdx.x;
    int tid = threadIdx.x;
    if (bx < 1536) {
        int vtile = (bx & 511) * 64;
        int m = bx >> 9;
        gemmL_body(smf, vtile, m, tid, X, W1, b1, W2, W3, b3);
    } else {
        csr_body((int*)smf, bx - 1536, tid, ei, ea);
    }
}

// plain leconv layer gemm: grid (512, 3) — R10/R15-proven
__global__ void __launch_bounds__(256) gemmL_k(const float* __restrict__ X,
                                               const float* __restrict__ W1,
                                               const float* __restrict__ b1,
                                               const float* __restrict__ W2,
                                               const float* __restrict__ W3,
                                               const float* __restrict__ b3) {
    __shared__ __align__(16) float sm[2 * 64 * TSTR];
    gemmL_body(sm, blockIdx.x * 64, blockIdx.y, threadIdx.x, X, W1, b1, W2, W3, b3);
}

// MLP projection, merged f-tiles: grid (Nn/64, 2): y=0 -> PA, y=1 -> PB. (R15-proven)
__global__ void __launch_bounds__(256) gemmM_k(const float* __restrict__ X,
                                               const float* __restrict__ Wm1,
                                               const float* __restrict__ bm1) {
    __shared__ __align__(16) float Xs[64 * TSTR];
    __shared__ __align__(16) float Ws[64 * TSTR];
    int tid = threadIdx.x;
    int vtile = blockIdx.x * 64;
    int isB = blockIdx.y;
    int koff = isB ? 64 : 0;
    float* Y = isB ? g_PB : g_PA;

    load_tile(Xs, X + vtile * 64, 64, tid);

    int tf = tid & 15, tv = tid >> 4;

#pragma unroll 1
    for (int ft = 0; ft < 4; ft++) {
        int ftile = ft * 64;
        load_tile(Ws, Wm1 + ftile * 128 + koff, 128, tid);
        __syncthreads();

        unsigned long long acc[4][4];
#pragma unroll
        for (int i = 0; i < 4; i++)
#pragma unroll
            for (int j = 0; j < 4; j++) acc[i][j] = 0ull;

        gemm_core(Xs, Ws, tf, tv, acc);

        float bj[4] = {0.f, 0.f, 0.f, 0.f};
        if (!isB) {
#pragma unroll
            for (int j = 0; j < 4; j++) bj[j] = bm1[ftile + tf + 16 * j];
        }
#pragma unroll
        for (int i = 0; i < 4; i++)
#pragma unroll
            for (int j = 0; j < 4; j++)
                Y[(vtile + tv + 16 * i) * 256 + ftile + tf + 16 * j] = red2(acc[i][j]) + bj[j];
        __syncthreads();
    }
}

// ---------------- gather-aggregate + combine, 4x unrolled (R10-proven) -------------
__global__ void aggc_k(const float* __restrict__ A, const float* __restrict__ B,
                       const float* __restrict__ C, float* __restrict__ H, int doRelu) {
    int warp = blockIdx.x * (blockDim.x >> 5) + (threadIdx.x >> 5);
    int lane = threadIdx.x & 31;
    if (warp >= Nn) return;
    int v = warp;
    int s = g_start[v];
    int g = v >> 8;
    int e = ((v & 255) == 255) ? (g * EPG + EPG) : g_start[v + 1];
    int abase = g * NPG * 64;
    float2 acc = make_float2(0.f, 0.f);
    float ws = 0.f;
    int i = s;
    for (; i + 4 <= e; i += 4) {
        int r0 = g_rows[i],     r1 = g_rows[i + 1];
        int r2 = g_rows[i + 2], r3 = g_rows[i + 3];
        float w0 = g_ews[i],     w1 = g_ews[i + 1];
        float w2 = g_ews[i + 2], w3 = g_ews[i + 3];
        float2 a0 = *(const float2*)&A[abase + r0 * 64 + lane * 2];
        float2 a1 = *(const float2*)&A[abase + r1 * 64 + lane * 2];
        float2 a2 = *(const float2*)&A[abase + r2 * 64 + lane * 2];
        float2 a3 = *(const float2*)&A[abase + r3 * 64 + lane * 2];
        acc.x += w0 * a0.x + w1 * a1.x + w2 * a2.x + w3 * a3.x;
        acc.y += w0 * a0.y + w1 * a1.y + w2 * a2.y + w3 * a3.y;
        ws += w0 + w1 + w2 + w3;
    }
    for (; i < e; i++) {
        int r = g_rows[i];
        float w = g_ews[i];
        float2 a = *(const float2*)&A[abase + r * 64 + lane * 2];
        acc.x += w * a.x;
        acc.y += w * a.y;
        ws += w;
    }
    float2 bv = *(const float2*)&B[v * 64 + lane * 2];
    float2 cv = *(const float2*)&C[v * 64 + lane * 2];
    float hx = acc.x - ws * bv.x + cv.x;
    float hy = acc.y - ws * bv.y + cv.y;
    if (doRelu) { hx = fmaxf(hx, 0.f); hy = fmaxf(hy, 0.f); }
    *(float2*)&H[v * 64 + lane * 2] = make_float2(hx, hy);
}

// ---------------- per-edge score: smem-staged packed-f32x2 relu-dot (R10 config) ----------------
#define ESTRIDE 68
__global__ void __launch_bounds__(512) edge_score_k(const int* __restrict__ ei,
                                                    const float* __restrict__ PA,
                                                    const float* __restrict__ PB,
                                                    const float* __restrict__ Wm2,
                                                    const float* __restrict__ bm2,
                                                    float* __restrict__ out) {
    extern __shared__ float sm[];
    float* pa_s = sm;                     // 256*ESTRIDE
    float* pb_s = sm + 256 * ESTRIDE;     // 256*ESTRIDE
    __shared__ __align__(16) float wm2s[256];
    int g = blockIdx.x, tid = threadIdx.x;
    if (tid < 256) wm2s[tid] = Wm2[tid];
    int base = g * EPG;

    int r[8], c[8];
    unsigned long long acc2[8];
#pragma unroll
    for (int i = 0; i < 8; i++) {
        int j = tid + i * 512;
        r[i] = ei[base + j] - g * NPG;
        c[i] = ei[En + base + j] - g * NPG;
        acc2[i] = 0ull;
    }

    for (int p = 0; p < 4; p++) {
        __syncthreads();
        for (int t = tid; t < 4096; t += 512) {
            int nd = t >> 4, kk = (t & 15) * 4;
            *(float4*)&pa_s[nd * ESTRIDE + kk] = *(const float4*)&PA[(g * NPG + nd) * 256 + p * 64 + kk];
            *(float4*)&pb_s[nd * ESTRIDE + kk] = *(const float4*)&PB[(g * NPG + nd) * 256 + p * 64 + kk];
        }
        __syncthreads();
#pragma unroll 4
        for (int kk = 0; kk < 64; kk += 4) {
            ulonglong2 w2 = *(const ulonglong2*)&wm2s[p * 64 + kk];
#pragma unroll
            for (int i = 0; i < 8; i++) {
                ulonglong2 va = *(const ulonglong2*)&pa_s[r[i] * ESTRIDE + kk];
                ulonglong2 vb = *(const ulonglong2*)&pb_s[c[i] * ESTRIDE + kk];
                unsigned long long s0 = relu2(add2(va.x, vb.x));
                unsigned long long s1 = relu2(add2(va.y, vb.y));
                fma2(acc2[i], s0, w2.x);
                fma2(acc2[i], s1, w2.y);
            }
        }
    }
    float bb = bm2[0];
#pragma unroll
    for (int i = 0; i < 8; i++) out[base + tid + i * 512] = red2(acc2[i]) + bb;
}

// ---------------- per-group stable bitonic argsort (R10 smem version) ----------------
__global__ void __launch_bounds__(1024) sort_k(const int* __restrict__ ei,
                                               float* __restrict__ out) {
    __shared__ unsigned long long keys[EPG];
    int g = blockIdx.x, tid = threadIdx.x;
    int base = g * EPG;
    for (int j = tid; j < EPG; j += 1024) {
        float s = out[base + j];
        unsigned int b = __float_as_uint(s);
        unsigned int enc = (b & 0x80000000u) ? ~b : (b | 0x80000000u);
        keys[j] = (((unsigned long long)(~enc)) << 32) | (unsigned int)j;
    }
    __syncthreads();
    for (int size = 2; size <= EPG; size <<= 1) {
        for (int stride = size >> 1; stride > 0; stride >>= 1) {
#pragma unroll 2
            for (int t = tid; t < EPG / 2; t += 1024) {
                int lo = ((t & ~(stride - 1)) << 1) | (t & (stride - 1));
                int hi = lo + stride;
                bool asc = ((lo & size) == 0);
                unsigned long long a = keys[lo], b = keys[hi];
                bool sw = asc ? (a > b) : (a < b);
                if (sw) { keys[lo] = b; keys[hi] = a; }
            }
            __syncthreads();
        }
    }
    for (int i2 = tid; i2 < EPG; i2 += 1024) {
        unsigned long long kv = keys[i2];
        int j = (int)(kv & 0xffffffffull);
        unsigned int enc = ~(unsigned int)(kv >> 32);
        unsigned int sb = (enc & 0x80000000u) ? (enc & 0x7fffffffu) : ~enc;
        float s = __uint_as_float(sb);
        int e = base + j;
        int rs = ei[e];
        int rd = ei[En + e];
        if (i2 < Kk) {
            int o = g * Kk + i2;
            out[OFF_CW + o] = s;
            g_keepnodes[o] = rs;
            g_keepnodes[GKn + o] = rd;
            g_presC[rs] = 1;
            g_presC[rd] = 1;
        } else {
            int o = g * Kk + (i2 - Kk);
            out[OFF_DW + o] = -s;
            g_dropnodes[o] = rs;
            g_dropnodes[GKn + o] = rd;
            g_presD[rs] = 1;
            g_presD[rd] = 1;
        }
    }
}

// ---------------- merged scans (y=0: causal, y=1: conf) — R10-proven ----------------
__global__ void __launch_bounds__(1024) scan1_k() {
    __shared__ int ws_[32];
    const int* pres = blockIdx.y ? g_presD : g_presC;
    int* nid = blockIdx.y ? g_nidD : g_nidC;
    int* bsum = blockIdx.y ? g_bsD : g_bsC;
    int i = blockIdx.x * 1024 + threadIdx.x;
    int x = pres[i];
    int v = warp_incl_scan(x);
    int w = threadIdx.x >> 5, lane = threadIdx.x & 31;
    if (lane == 31) ws_[w] = v;
    __syncthreads();
    if (w == 0) { int t = ws_[lane]; t = warp_incl_scan(t); ws_[lane] = t; }
    __syncthreads();
    if (w > 0) v += ws_[w - 1];
    nid[i] = v;
    if (threadIdx.x == 1023) bsum[blockIdx.x] = v;
}

__global__ void scan2_k() {
    int* bsum = (threadIdx.x >= 32) ? g_bsD : g_bsC;
    int idx = threadIdx.x & 31;
    int x = bsum[idx];
    int v = warp_incl_scan(x);
    bsum[idx] = v - x;
}

__global__ void __launch_bounds__(1024) scan3_k(float* __restrict__ out) {
    const int* pres = blockIdx.y ? g_presD : g_presC;
    int* nid = blockIdx.y ? g_nidD : g_nidC;
    const int* bsum = blockIdx.y ? g_bsD : g_bsC;
    float* maskOut = out + (blockIdx.y ? OFF_FMASK : OFF_CMASK);
    int i = blockIdx.x * 1024 + threadIdx.x;
    nid[i] = nid[i] + bsum[blockIdx.x] - 1;
    maskOut[i] = (float)pres[i];
}

// ---------------- final relabeled-edge gather ----------------
__global__ void gather_k(float* __restrict__ out) {
    int i = blockIdx.x * blockDim.x + threadIdx.x;
    if (i >= 2 * GKn) return;
    out[OFF_CEI + i] = (float)g_nidC[g_keepnodes[i]];
    out[OFF_FEI + i] = (float)g_nidD[g_dropnodes[i]];
}

// ---------------- host launch ----------------
extern "C" void kernel_launch(void* const* d_in, const int* in_sizes, int n_in,
                              void* d_out, int out_size) {
    const float* x   = (const float*)d_in[0];
    const float* ea  = (const float*)d_in[1];
    const float* W11 = (const float*)d_in[2];
    const float* b11 = (const float*)d_in[3];
    const float* W12 = (const float*)d_in[4];
    const float* W13 = (const float*)d_in[5];
    const float* b13 = (const float*)d_in[6];
    const float* W21 = (const float*)d_in[7];
    const float* b21 = (const float*)d_in[8];
    const float* W22 = (const float*)d_in[9];
    const float* W23 = (const float*)d_in[10];
    const float* b23 = (const float*)d_in[11];
    const float* Wm1 = (const float*)d_in[12];
    const float* bm1 = (const float*)d_in[13];
    const float* Wm2 = (const float*)d_in[14];
    const float* bm2 = (const float*)d_in[15];
    const int*   ei  = (const int*)d_in[16];   // int32 (JAX x64 disabled)
    float* out = (float*)d_out;

    float *A, *B, *C, *H1, *H2, *PA, *PB;
    cudaGetSymbolAddress((void**)&A, g_A);
    cudaGetSymbolAddress((void**)&B, g_B);
    cudaGetSymbolAddress((void**)&C, g_C);
    cudaGetSymbolAddress((void**)&H1, g_H1);
    cudaGetSymbolAddress((void**)&H2, g_H2);
    cudaGetSymbolAddress((void**)&PA, g_PA);
    cudaGetSymbolAddress((void**)&PB, g_PB);

    const int f1Smem = 2 * 64 * TSTR * sizeof(float);     // 34816 B (>= csr's 8228 B)
    const int esSmem = 2 * 256 * ESTRIDE * sizeof(float); // 136 KB
    cudaFuncSetAttribute(edge_score_k, cudaFuncAttributeMaxDynamicSharedMemorySize, esSmem);

    // ---- leconv 1 gemm FUSED with csr build (independent work, one launch) ----
    fused1_k<<<1536 + Gn, 256, f1Smem>>>(x, W11, b11, W12, W13, b13, ei, ea);
    aggc_k<<<Nn / 8, 256>>>(A, B, C, H1, 1);

    // ---- leconv 2 ----
    gemmL_k<<<dim3(Nn / 64, 3), 256>>>(H1, W21, b21, W22, W23, b23);
    aggc_k<<<Nn / 8, 256>>>(A, B, C, H2, 0);

    // ---- MLP node projections (PA | PB), merged f-tiles ----
    gemmM_k<<<dim3(Nn / 64, 2), 256>>>(H2, Wm1, bm1);

    // ---- per-edge scores ----
    edge_score_k<<<Gn, 512, esSmem>>>(ei, PA, PB, Wm2, bm2, out);

    // ---- per-group sort + keep/drop split ----
    sort_k<<<Gn, 1024>>>(ei, out);

    // ---- relabel scans (both graphs, merged) ----
    scan1_k<<<dim3(32, 2), 1024>>>();
    scan2_k<<<1, 64>>>();
    scan3_k<<<dim3(32, 2), 1024>>>(out);

    // ---- relabeled edge index gather ----
    gather_k<<<(2 * GKn) / 256, 256>>>(out);
}